// round 1
// baseline (speedup 1.0000x reference)
#include <cuda_runtime.h>
#include <math.h>
#include <stdint.h>

#define V   50257
#define EMB 1024
#define HD  1024
#define HE  1024
#define L   128
#define B   64
#define CAT 2048   // EMB + HD
#define G3  3072   // 3 * HD

// ---------------- scratch (device globals: no allocations allowed) ----------
__device__ float g_attn_in[B * CAT];      // [embedded | h0]
__device__ float g_comb_in[B * CAT];      // [embedded | ctx]
__device__ float g_attn_logits[B * L];
__device__ float g_x[B * HE];             // relu(comb)
__device__ float g_gi[B * G3];
__device__ float g_gh[B * G3];
__device__ float g_logits[B * V];

// ---------------- kernel 1: embedding lookup + concat builds ----------------
__global__ void embed_concat_kernel(const int* __restrict__ idx,
                                    const float* __restrict__ hidden,
                                    const float* __restrict__ emb_table) {
    int b = blockIdx.x;
    int row = idx[b];
    for (int k = threadIdx.x; k < EMB; k += blockDim.x) {
        float e = emb_table[(size_t)row * EMB + k];
        g_attn_in[b * CAT + k] = e;
        g_comb_in[b * CAT + k] = e;
        g_attn_in[b * CAT + EMB + k] = hidden[b * HD + k];
    }
}

// ---------------- generic tiled SGEMM: C[64,N] = act(A[64,K] @ W[N,K]^T + b) -
// BM=64, BN=64, BK=16, 256 threads, 4x4 micro-tile per thread.
template <int ACT>
__global__ void gemm64_kernel(const float* __restrict__ A,
                              const float* __restrict__ W,
                              const float* __restrict__ bias,
                              float* __restrict__ C,
                              int N, int K) {
    __shared__ float As[16][64 + 4];
    __shared__ float Ws[16][64 + 4];

    const int tid = threadIdx.x;
    const int n0  = blockIdx.x * 64;
    const int lr  = tid >> 2;          // 0..63  (row for loading)
    const int lk  = (tid & 3) * 4;     // 0,4,8,12
    const int tx  = tid & 15;          // 0..15  (output col group)
    const int ty  = tid >> 4;          // 0..15  (output row group)

    float acc[4][4];
#pragma unroll
    for (int i = 0; i < 4; i++)
#pragma unroll
        for (int j = 0; j < 4; j++) acc[i][j] = 0.0f;

    for (int k0 = 0; k0 < K; k0 += 16) {
        // Load A tile (transposed into k-major)
        float4 a4 = *reinterpret_cast<const float4*>(&A[(size_t)lr * K + k0 + lk]);
        As[lk + 0][lr] = a4.x;
        As[lk + 1][lr] = a4.y;
        As[lk + 2][lr] = a4.z;
        As[lk + 3][lr] = a4.w;
        // Load W tile (transposed into k-major), bounds-guarded on N
        float4 w4 = make_float4(0.f, 0.f, 0.f, 0.f);
        int n = n0 + lr;
        if (n < N)
            w4 = *reinterpret_cast<const float4*>(&W[(size_t)n * K + k0 + lk]);
        Ws[lk + 0][lr] = w4.x;
        Ws[lk + 1][lr] = w4.y;
        Ws[lk + 2][lr] = w4.z;
        Ws[lk + 3][lr] = w4.w;
        __syncthreads();

#pragma unroll
        for (int k = 0; k < 16; k++) {
            float4 av = *reinterpret_cast<const float4*>(&As[k][ty * 4]);
            float4 wv = *reinterpret_cast<const float4*>(&Ws[k][tx * 4]);
            float am[4] = {av.x, av.y, av.z, av.w};
            float wn[4] = {wv.x, wv.y, wv.z, wv.w};
#pragma unroll
            for (int i = 0; i < 4; i++)
#pragma unroll
                for (int j = 0; j < 4; j++)
                    acc[i][j] = fmaf(am[i], wn[j], acc[i][j]);
        }
        __syncthreads();
    }

#pragma unroll
    for (int j = 0; j < 4; j++) {
        int n = n0 + tx * 4 + j;
        if (n >= N) continue;
        float bv = bias[n];
#pragma unroll
        for (int i = 0; i < 4; i++) {
            float v = acc[i][j] + bv;
            if (ACT == 1) v = fmaxf(v, 0.0f);
            C[(size_t)(ty * 4 + i) * N + n] = v;
        }
    }
}

// ---------------- attention softmax over L=128 ------------------------------
__global__ void attn_softmax_kernel(float* __restrict__ out_attn) {
    int b = blockIdx.x;
    int t = threadIdx.x;  // 0..127
    __shared__ float red[4];
    float v = g_attn_logits[b * L + t];
    float m = v;
#pragma unroll
    for (int o = 16; o; o >>= 1) m = fmaxf(m, __shfl_xor_sync(0xffffffffu, m, o));
    if ((t & 31) == 0) red[t >> 5] = m;
    __syncthreads();
    m = fmaxf(fmaxf(red[0], red[1]), fmaxf(red[2], red[3]));
    __syncthreads();
    float e = expf(v - m);
    float s = e;
#pragma unroll
    for (int o = 16; o; o >>= 1) s += __shfl_xor_sync(0xffffffffu, s, o);
    if ((t & 31) == 0) red[t >> 5] = s;
    __syncthreads();
    s = red[0] + red[1] + red[2] + red[3];
    out_attn[b * L + t] = e / s;
}

// ---------------- context: ctx[b,e] = sum_l attn[b,l] * enc[l,b,e] ----------
__global__ void context_kernel(const float* __restrict__ enc,
                               const float* __restrict__ attn) {
    int b = blockIdx.x;
    __shared__ float aw[L];
    for (int l = threadIdx.x; l < L; l += blockDim.x) aw[l] = attn[b * L + l];
    __syncthreads();
    for (int e = threadIdx.x; e < HE; e += blockDim.x) {
        float s = 0.0f;
#pragma unroll 8
        for (int l = 0; l < L; l++)
            s = fmaf(aw[l], enc[((size_t)l * B + b) * HE + e], s);
        g_comb_in[b * CAT + EMB + e] = s;
    }
}

// ---------------- GRU elementwise (PyTorch r,z,n gate layout) ---------------
__global__ void gru_kernel(const float* __restrict__ hidden,
                           float* __restrict__ hnew_out) {
    int b = blockIdx.x;
    for (int j = threadIdx.x; j < HD; j += blockDim.x) {
        float ir = g_gi[b * G3 + j];
        float iz = g_gi[b * G3 + HD + j];
        float in_ = g_gi[b * G3 + 2 * HD + j];
        float hr = g_gh[b * G3 + j];
        float hz = g_gh[b * G3 + HD + j];
        float hn = g_gh[b * G3 + 2 * HD + j];
        float r = 1.0f / (1.0f + expf(-(ir + hr)));
        float z = 1.0f / (1.0f + expf(-(iz + hz)));
        float n = tanhf(in_ + r * hn);
        float h0 = hidden[b * HD + j];
        hnew_out[b * HD + j] = (1.0f - z) * n + z * h0;
    }
}

// ---------------- row log_softmax over V=50257 ------------------------------
__global__ void logsoftmax_kernel(float* __restrict__ out) {
    int b = blockIdx.x;
    int t = threadIdx.x;   // 256 threads
    __shared__ float red[8];
    const float* row = &g_logits[(size_t)b * V];

    float m = -INFINITY;
    for (int v = t; v < V; v += 256) m = fmaxf(m, row[v]);
#pragma unroll
    for (int o = 16; o; o >>= 1) m = fmaxf(m, __shfl_xor_sync(0xffffffffu, m, o));
    if ((t & 31) == 0) red[t >> 5] = m;
    __syncthreads();
    float M = red[0];
#pragma unroll
    for (int w = 1; w < 8; w++) M = fmaxf(M, red[w]);
    __syncthreads();

    float s = 0.0f;
    for (int v = t; v < V; v += 256) s += expf(row[v] - M);
#pragma unroll
    for (int o = 16; o; o >>= 1) s += __shfl_xor_sync(0xffffffffu, s, o);
    if ((t & 31) == 0) red[t >> 5] = s;
    __syncthreads();
    float S = 0.0f;
#pragma unroll
    for (int w = 0; w < 8; w++) S += red[w];
    float lse = M + logf(S);

    float* orow = &out[(size_t)b * V];
    for (int v = t; v < V; v += 256) orow[v] = row[v] - lse;
}

// ---------------- launcher --------------------------------------------------
extern "C" void kernel_launch(void* const* d_in, const int* in_sizes, int n_in,
                              void* d_out, int out_size) {
    const int*   input_tensor = (const int*)  d_in[0];   // [1,B]
    const float* hidden       = (const float*)d_in[1];   // [1,B,HD]
    const float* enc          = (const float*)d_in[2];   // [L,B,HE]
    // d_in[3] = batch_size (scalar), unused
    const float* emb_table    = (const float*)d_in[4];   // [V,EMB]
    const float* attn_w       = (const float*)d_in[5];   // [L, CAT]
    const float* attn_b       = (const float*)d_in[6];   // [L]
    const float* comb_w       = (const float*)d_in[7];   // [HE, CAT]
    const float* comb_b       = (const float*)d_in[8];   // [HE]
    const float* w_ih         = (const float*)d_in[9];   // [G3, HE]
    const float* w_hh         = (const float*)d_in[10];  // [G3, HD]
    const float* b_ih         = (const float*)d_in[11];  // [G3]
    const float* b_hh         = (const float*)d_in[12];  // [G3]
    const float* out_w        = (const float*)d_in[13];  // [V, HD]
    const float* out_b        = (const float*)d_in[14];  // [V]

    float* out        = (float*)d_out;
    float* out_logsm  = out;                       // [B, V]
    float* out_hnew   = out + (size_t)B * V;       // [B, HD]  (== h_new[0])
    float* out_attn   = out + (size_t)B * V + (size_t)B * HD;  // [B, L]

    float* d_attn_in;     cudaGetSymbolAddress((void**)&d_attn_in,     g_attn_in);
    float* d_comb_in;     cudaGetSymbolAddress((void**)&d_comb_in,     g_comb_in);
    float* d_attn_logits; cudaGetSymbolAddress((void**)&d_attn_logits, g_attn_logits);
    float* d_x;           cudaGetSymbolAddress((void**)&d_x,           g_x);
    float* d_gi;          cudaGetSymbolAddress((void**)&d_gi,          g_gi);
    float* d_gh;          cudaGetSymbolAddress((void**)&d_gh,          g_gh);
    float* d_logits;      cudaGetSymbolAddress((void**)&d_logits,      g_logits);

    // 1. embedding + concats
    embed_concat_kernel<<<B, 256>>>(input_tensor, hidden, emb_table);

    // 2. attention logits: [B,CAT] @ attn_w[L,CAT]^T
    gemm64_kernel<0><<<(L + 63) / 64, 256>>>(d_attn_in, attn_w, attn_b,
                                             d_attn_logits, L, CAT);

    // 3. softmax over L
    attn_softmax_kernel<<<B, L>>>(out_attn);

    // 4. context
    context_kernel<<<B, 256>>>(enc, out_attn);

    // 5. comb + relu: [B,CAT] @ comb_w[HE,CAT]^T
    gemm64_kernel<1><<<(HE + 63) / 64, 256>>>(d_comb_in, comb_w, comb_b,
                                              d_x, HE, CAT);

    // 6. GRU input/hidden GEMMs
    gemm64_kernel<0><<<(G3 + 63) / 64, 256>>>(d_x, w_ih, b_ih, d_gi, G3, HE);
    gemm64_kernel<0><<<(G3 + 63) / 64, 256>>>(hidden, w_hh, b_hh, d_gh, G3, HD);

    // 7. GRU elementwise -> h_new (written straight into output region)
    gru_kernel<<<B, 256>>>(hidden, out_hnew);

    // 8. output projection: [B,HD] @ out_w[V,HD]^T
    gemm64_kernel<0><<<(V + 63) / 64, 256>>>(out_hnew, out_w, out_b,
                                             d_logits, V, HD);

    // 9. log_softmax over V
    logsoftmax_kernel<<<B, 256>>>(out_logsm);
}

// round 2
// speedup vs baseline: 3.7487x; 3.7487x over previous
#include <cuda_runtime.h>
#include <cuda_bf16.h>
#include <math.h>
#include <stdint.h>

#define V   50257
#define EMB 1024
#define HD  1024
#define HE  1024
#define L   128
#define B   64
#define CAT 2048   // EMB + HD
#define G3  3072   // 3 * HD

// ---------------- scratch (device globals: no allocations allowed) ----------
__device__ float g_attn_in[B * CAT];      // [embedded | h0]
__device__ float g_comb_in[B * CAT];      // [embedded | ctx]
__device__ float g_attn_logits[B * L];
__device__ float g_x[B * HE];             // comb accumulator (pre-relu)
__device__ float g_gi[B * G3];
__device__ float g_gh[B * G3];
__device__ float g_logits[B * V];
__device__ __nv_bfloat16 g_h_bf16[B * HD];

// ---------------- kernel 1: embedding lookup + concat builds ----------------
__global__ void embed_concat_kernel(const int* __restrict__ idx,
                                    const float* __restrict__ hidden,
                                    const float* __restrict__ emb_table) {
    int b = blockIdx.x;
    int row = idx[b];
    for (int k = threadIdx.x; k < EMB; k += blockDim.x) {
        float e = emb_table[(size_t)row * EMB + k];
        g_attn_in[b * CAT + k] = e;
        g_comb_in[b * CAT + k] = e;
        g_attn_in[b * CAT + EMB + k] = hidden[b * HD + k];
    }
}

// ---------------- bias init for K-split atomic GEMMs ------------------------
// segments: attn_logits (B*L), g_x (B*HE), g_gi (B*G3), g_gh (B*G3)
#define SEG0 (B * L)
#define SEG1 (SEG0 + B * HE)
#define SEG2 (SEG1 + B * G3)
#define SEG3 (SEG2 + B * G3)
__global__ void init_bias_kernel(const float* __restrict__ attn_b,
                                 const float* __restrict__ comb_b,
                                 const float* __restrict__ b_ih,
                                 const float* __restrict__ b_hh) {
    int i = blockIdx.x * 256 + threadIdx.x;
    if (i < SEG0) {
        g_attn_logits[i] = attn_b[i & (L - 1)];
    } else if (i < SEG1) {
        int j = i - SEG0; g_x[j] = comb_b[j & (HE - 1)];
    } else if (i < SEG2) {
        int j = i - SEG1; g_gi[j] = b_ih[j % G3];
    } else if (i < SEG3) {
        int j = i - SEG2; g_gh[j] = b_hh[j % G3];
    }
}

// ------ K-split tiled SGEMM: C[64,N] += A[64,K(chunk)] @ W[N,K]^T -----------
// grid (nBlocks, kChunks); BM=64, BN=64, BK=16; atomicAdd epilogue.
template <int RELU_A>
__global__ void gemm_ksplit_kernel(const float* __restrict__ A,
                                   const float* __restrict__ W,
                                   float* __restrict__ C,
                                   int N, int K, int Kc) {
    __shared__ float As[16][64 + 4];
    __shared__ float Ws[16][64 + 4];

    const int tid = threadIdx.x;
    const int n0  = blockIdx.x * 64;
    const int kbase = blockIdx.y * Kc;
    const int lr  = tid >> 2;          // 0..63
    const int lk  = (tid & 3) * 4;     // 0,4,8,12
    const int tx  = tid & 15;
    const int ty  = tid >> 4;

    float acc[4][4];
#pragma unroll
    for (int i = 0; i < 4; i++)
#pragma unroll
        for (int j = 0; j < 4; j++) acc[i][j] = 0.0f;

    for (int k0 = kbase; k0 < kbase + Kc; k0 += 16) {
        float4 a4 = *reinterpret_cast<const float4*>(&A[(size_t)lr * K + k0 + lk]);
        if (RELU_A) {
            a4.x = fmaxf(a4.x, 0.f); a4.y = fmaxf(a4.y, 0.f);
            a4.z = fmaxf(a4.z, 0.f); a4.w = fmaxf(a4.w, 0.f);
        }
        As[lk + 0][lr] = a4.x; As[lk + 1][lr] = a4.y;
        As[lk + 2][lr] = a4.z; As[lk + 3][lr] = a4.w;
        float4 w4 = make_float4(0.f, 0.f, 0.f, 0.f);
        int n = n0 + lr;
        if (n < N)
            w4 = *reinterpret_cast<const float4*>(&W[(size_t)n * K + k0 + lk]);
        Ws[lk + 0][lr] = w4.x; Ws[lk + 1][lr] = w4.y;
        Ws[lk + 2][lr] = w4.z; Ws[lk + 3][lr] = w4.w;
        __syncthreads();

#pragma unroll
        for (int k = 0; k < 16; k++) {
            float4 av = *reinterpret_cast<const float4*>(&As[k][ty * 4]);
            float4 wv = *reinterpret_cast<const float4*>(&Ws[k][tx * 4]);
            float am[4] = {av.x, av.y, av.z, av.w};
            float wn[4] = {wv.x, wv.y, wv.z, wv.w};
#pragma unroll
            for (int i = 0; i < 4; i++)
#pragma unroll
                for (int j = 0; j < 4; j++)
                    acc[i][j] = fmaf(am[i], wn[j], acc[i][j]);
        }
        __syncthreads();
    }

#pragma unroll
    for (int j = 0; j < 4; j++) {
        int n = n0 + tx * 4 + j;
        if (n >= N) continue;
#pragma unroll
        for (int i = 0; i < 4; i++)
            atomicAdd(&C[(size_t)(ty * 4 + i) * N + n], acc[i][j]);
    }
}

// ---------------- attention softmax over L=128 ------------------------------
__global__ void attn_softmax_kernel(float* __restrict__ out_attn) {
    int b = blockIdx.x;
    int t = threadIdx.x;  // 0..127
    __shared__ float red[4];
    float v = g_attn_logits[b * L + t];
    float m = v;
#pragma unroll
    for (int o = 16; o; o >>= 1) m = fmaxf(m, __shfl_xor_sync(0xffffffffu, m, o));
    if ((t & 31) == 0) red[t >> 5] = m;
    __syncthreads();
    m = fmaxf(fmaxf(red[0], red[1]), fmaxf(red[2], red[3]));
    __syncthreads();
    float e = expf(v - m);
    float s = e;
#pragma unroll
    for (int o = 16; o; o >>= 1) s += __shfl_xor_sync(0xffffffffu, s, o);
    if ((t & 31) == 0) red[t >> 5] = s;
    __syncthreads();
    s = red[0] + red[1] + red[2] + red[3];
    out_attn[b * L + t] = e / s;
}

// ---------------- context: ctx[b,e] = sum_l attn[b,l] * enc[l,b,e] ----------
// grid (B, 4): each block handles a 256-wide e-chunk, one e per thread.
__global__ void context_kernel(const float* __restrict__ enc,
                               const float* __restrict__ attn) {
    int b = blockIdx.x;
    int e = blockIdx.y * 256 + threadIdx.x;
    __shared__ float aw[L];
    if (threadIdx.x < L) aw[threadIdx.x] = attn[b * L + threadIdx.x];
    __syncthreads();
    float s = 0.0f;
#pragma unroll 8
    for (int l = 0; l < L; l++)
        s = fmaf(aw[l], enc[((size_t)l * B + b) * HE + e], s);
    g_comb_in[b * CAT + EMB + e] = s;
}

// ---------------- GRU elementwise (PyTorch r,z,n gate layout) ---------------
__global__ void gru_kernel(const float* __restrict__ hidden,
                           float* __restrict__ hnew_out) {
    int b = blockIdx.x;
    for (int j = threadIdx.x; j < HD; j += blockDim.x) {
        float ir = g_gi[b * G3 + j];
        float iz = g_gi[b * G3 + HD + j];
        float in_ = g_gi[b * G3 + 2 * HD + j];
        float hr = g_gh[b * G3 + j];
        float hz = g_gh[b * G3 + HD + j];
        float hn = g_gh[b * G3 + 2 * HD + j];
        float r = 1.0f / (1.0f + expf(-(ir + hr)));
        float z = 1.0f / (1.0f + expf(-(iz + hz)));
        float n = tanhf(in_ + r * hn);
        float h0 = hidden[b * HD + j];
        float h = (1.0f - z) * n + z * h0;
        hnew_out[b * HD + j] = h;
        g_h_bf16[b * HD + j] = __float2bfloat16(h);
    }
}

// -------- output projection: bf16 mma.sync, fp32 accumulate -----------------
// C[64, V] = A_bf16[64,1024] @ W[V,1024]^T + bias,  W converted fp32->bf16 on the fly.
// 256 threads = 8 warps: 4 warps along M (16 rows each) x 2 warps along N (32 cols).
__global__ void __launch_bounds__(256)
out_proj_mma_kernel(const float* __restrict__ W,
                    const float* __restrict__ bias,
                    float* __restrict__ Cout) {
    const int n0   = blockIdx.x * 64;
    const int tid  = threadIdx.x;
    const int wid  = tid >> 5, lane = tid & 31;
    const int wm   = wid & 3;   // m-warp: rows 16*wm
    const int wn   = wid >> 2;  // n-warp: cols 32*wn
    const int g    = lane >> 2, t = lane & 3;

    __shared__ __nv_bfloat16 sA[2][64][36];  // stride 36 bf16 = 72B (pad)
    __shared__ __nv_bfloat16 sW[2][64][36];

    // global load thread mapping
    const int wrow0 = tid >> 3;          // 0..31
    const int wc4   = (tid & 7) * 4;     // 0..28 step 4
    const int wrow1 = wrow0 + 32;        // 32..63
    const int arow  = tid >> 2;          // 0..63
    const int ac8   = (tid & 3) * 8;     // 0,8,16,24

    float4 wv0, wv1;
    uint4  av;

    auto load_g = [&](int k0) {
        int nn0 = n0 + wrow0, nn1 = n0 + wrow1;
        wv0 = (nn0 < V) ? *reinterpret_cast<const float4*>(W + (size_t)nn0 * 1024 + k0 + wc4)
                        : make_float4(0.f, 0.f, 0.f, 0.f);
        wv1 = (nn1 < V) ? *reinterpret_cast<const float4*>(W + (size_t)nn1 * 1024 + k0 + wc4)
                        : make_float4(0.f, 0.f, 0.f, 0.f);
        av  = *reinterpret_cast<const uint4*>(g_h_bf16 + arow * 1024 + k0 + ac8);
    };
    auto store_s = [&](int buf) {
        *reinterpret_cast<__nv_bfloat162*>(&sW[buf][wrow0][wc4 + 0]) =
            __float22bfloat162_rn(make_float2(wv0.x, wv0.y));
        *reinterpret_cast<__nv_bfloat162*>(&sW[buf][wrow0][wc4 + 2]) =
            __float22bfloat162_rn(make_float2(wv0.z, wv0.w));
        *reinterpret_cast<__nv_bfloat162*>(&sW[buf][wrow1][wc4 + 0]) =
            __float22bfloat162_rn(make_float2(wv1.x, wv1.y));
        *reinterpret_cast<__nv_bfloat162*>(&sW[buf][wrow1][wc4 + 2]) =
            __float22bfloat162_rn(make_float2(wv1.z, wv1.w));
        *reinterpret_cast<unsigned*>(&sA[buf][arow][ac8 + 0]) = av.x;
        *reinterpret_cast<unsigned*>(&sA[buf][arow][ac8 + 2]) = av.y;
        *reinterpret_cast<unsigned*>(&sA[buf][arow][ac8 + 4]) = av.z;
        *reinterpret_cast<unsigned*>(&sA[buf][arow][ac8 + 6]) = av.w;
    };

    float acc[4][4];
#pragma unroll
    for (int j = 0; j < 4; j++)
#pragma unroll
        for (int i = 0; i < 4; i++) acc[j][i] = 0.0f;

    auto compute = [&](int buf) {
#pragma unroll
        for (int ks = 0; ks < 2; ks++) {
            const int kb = ks * 16;
            unsigned a0 = *reinterpret_cast<const unsigned*>(&sA[buf][16 * wm + g][kb + 2 * t]);
            unsigned a1 = *reinterpret_cast<const unsigned*>(&sA[buf][16 * wm + g + 8][kb + 2 * t]);
            unsigned a2 = *reinterpret_cast<const unsigned*>(&sA[buf][16 * wm + g][kb + 2 * t + 8]);
            unsigned a3 = *reinterpret_cast<const unsigned*>(&sA[buf][16 * wm + g + 8][kb + 2 * t + 8]);
#pragma unroll
            for (int j = 0; j < 4; j++) {
                unsigned b0 = *reinterpret_cast<const unsigned*>(&sW[buf][32 * wn + 8 * j + g][kb + 2 * t]);
                unsigned b1 = *reinterpret_cast<const unsigned*>(&sW[buf][32 * wn + 8 * j + g][kb + 2 * t + 8]);
                asm volatile(
                    "mma.sync.aligned.m16n8k16.row.col.f32.bf16.bf16.f32 "
                    "{%0,%1,%2,%3}, {%4,%5,%6,%7}, {%8,%9}, {%0,%1,%2,%3};"
                    : "+f"(acc[j][0]), "+f"(acc[j][1]), "+f"(acc[j][2]), "+f"(acc[j][3])
                    : "r"(a0), "r"(a1), "r"(a2), "r"(a3), "r"(b0), "r"(b1));
            }
        }
    };

    load_g(0);
    store_s(0);
    __syncthreads();
#pragma unroll 1
    for (int it = 0; it < 32; it++) {
        if (it < 31) load_g((it + 1) * 32);
        compute(it & 1);
        if (it < 31) store_s((it + 1) & 1);
        __syncthreads();
    }

    // epilogue
    const int m = 16 * wm + g;
#pragma unroll
    for (int j = 0; j < 4; j++) {
        int n = n0 + 32 * wn + 8 * j + 2 * t;
        if (n < V) {
            float bv = bias[n];
            Cout[(size_t)m * V + n]       = acc[j][0] + bv;
            Cout[(size_t)(m + 8) * V + n] = acc[j][2] + bv;
        }
        if (n + 1 < V) {
            float bv = bias[n + 1];
            Cout[(size_t)m * V + n + 1]       = acc[j][1] + bv;
            Cout[(size_t)(m + 8) * V + n + 1] = acc[j][3] + bv;
        }
    }
}

// ---------------- row log_softmax over V=50257 (1024 threads) ---------------
__global__ void logsoftmax_kernel(float* __restrict__ out) {
    int b = blockIdx.x;
    int t = threadIdx.x;   // 1024 threads
    __shared__ float red[32];
    __shared__ float sM, sS;
    const float* row = &g_logits[(size_t)b * V];

    float m = -INFINITY;
    for (int v = t; v < V; v += 1024) m = fmaxf(m, row[v]);
#pragma unroll
    for (int o = 16; o; o >>= 1) m = fmaxf(m, __shfl_xor_sync(0xffffffffu, m, o));
    if ((t & 31) == 0) red[t >> 5] = m;
    __syncthreads();
    if (t < 32) {
        float x = red[t];
#pragma unroll
        for (int o = 16; o; o >>= 1) x = fmaxf(x, __shfl_xor_sync(0xffffffffu, x, o));
        if (t == 0) sM = x;
    }
    __syncthreads();
    float M = sM;

    float s = 0.0f;
    for (int v = t; v < V; v += 1024) s += expf(row[v] - M);
#pragma unroll
    for (int o = 16; o; o >>= 1) s += __shfl_xor_sync(0xffffffffu, s, o);
    if ((t & 31) == 0) red[t >> 5] = s;
    __syncthreads();
    if (t < 32) {
        float x = red[t];
#pragma unroll
        for (int o = 16; o; o >>= 1) x += __shfl_xor_sync(0xffffffffu, x, o);
        if (t == 0) sS = x;
    }
    __syncthreads();
    float lse = M + logf(sS);

    float* orow = &out[(size_t)b * V];
    for (int v = t; v < V; v += 1024) orow[v] = row[v] - lse;
}

// ---------------- launcher --------------------------------------------------
extern "C" void kernel_launch(void* const* d_in, const int* in_sizes, int n_in,
                              void* d_out, int out_size) {
    const int*   input_tensor = (const int*)  d_in[0];   // [1,B]
    const float* hidden       = (const float*)d_in[1];   // [1,B,HD]
    const float* enc          = (const float*)d_in[2];   // [L,B,HE]
    const float* emb_table    = (const float*)d_in[4];   // [V,EMB]
    const float* attn_w       = (const float*)d_in[5];   // [L, CAT]
    const float* attn_b       = (const float*)d_in[6];   // [L]
    const float* comb_w       = (const float*)d_in[7];   // [HE, CAT]
    const float* comb_b       = (const float*)d_in[8];   // [HE]
    const float* w_ih         = (const float*)d_in[9];   // [G3, HE]
    const float* w_hh         = (const float*)d_in[10];  // [G3, HD]
    const float* b_ih         = (const float*)d_in[11];  // [G3]
    const float* b_hh         = (const float*)d_in[12];  // [G3]
    const float* out_w        = (const float*)d_in[13];  // [V, HD]
    const float* out_b        = (const float*)d_in[14];  // [V]

    float* out        = (float*)d_out;
    float* out_logsm  = out;                                   // [B, V]
    float* out_hnew   = out + (size_t)B * V;                   // [B, HD]
    float* out_attn   = out + (size_t)B * V + (size_t)B * HD;  // [B, L]

    float* d_attn_in;     cudaGetSymbolAddress((void**)&d_attn_in,     g_attn_in);
    float* d_comb_in;     cudaGetSymbolAddress((void**)&d_comb_in,     g_comb_in);
    float* d_attn_logits; cudaGetSymbolAddress((void**)&d_attn_logits, g_attn_logits);
    float* d_x;           cudaGetSymbolAddress((void**)&d_x,           g_x);
    float* d_gi;          cudaGetSymbolAddress((void**)&d_gi,          g_gi);
    float* d_gh;          cudaGetSymbolAddress((void**)&d_gh,          g_gh);
    float* d_logits;      cudaGetSymbolAddress((void**)&d_logits,      g_logits);

    // 1. embedding + concats, bias init (independent)
    embed_concat_kernel<<<B, 256>>>(input_tensor, hidden, emb_table);
    init_bias_kernel<<<(SEG3 + 255) / 256, 256>>>(attn_b, comb_b, b_ih, b_hh);

    // 2. GRU hidden GEMM (only needs hidden + init) — run early
    gemm_ksplit_kernel<0><<<dim3(G3 / 64, 8), 256>>>(hidden, w_hh, d_gh, G3, HD, HD / 8);

    // 3. attention logits: [B,CAT] @ attn_w[L,CAT]^T
    gemm_ksplit_kernel<0><<<dim3(L / 64, 8), 256>>>(d_attn_in, attn_w, d_attn_logits, L, CAT, CAT / 8);

    // 4. softmax over L
    attn_softmax_kernel<<<B, L>>>(out_attn);

    // 5. context
    context_kernel<<<dim3(B, 4), 256>>>(enc, out_attn);

    // 6. comb GEMM (pre-relu accumulates into g_x)
    gemm_ksplit_kernel<0><<<dim3(HE / 64, 8), 256>>>(d_comb_in, comb_w, d_x, HE, CAT, CAT / 8);

    // 7. GRU input GEMM, relu folded into A-load
    gemm_ksplit_kernel<1><<<dim3(G3 / 64, 8), 256>>>(d_x, w_ih, d_gi, G3, HE, HE / 8);

    // 8. GRU elementwise -> h_new fp32 (output) + bf16 (for mma)
    gru_kernel<<<B, 256>>>(hidden, out_hnew);

    // 9. output projection via bf16 mma
    out_proj_mma_kernel<<<(V + 63) / 64, 256>>>(out_w, out_b, d_logits);

    // 10. log_softmax over V
    logsoftmax_kernel<<<B, 1024>>>(out_logsm);
}

// round 3
// speedup vs baseline: 5.2302x; 1.3952x over previous
#include <cuda_runtime.h>
#include <cuda_bf16.h>
#include <math.h>
#include <stdint.h>

#define V   50257
#define EMB 1024
#define HD  1024
#define HE  1024
#define L   128
#define B   64
#define CAT 2048   // EMB + HD
#define G3  3072   // 3 * HD

// ---------------- scratch (device globals) ----------------------------------
__device__ float         g_attn_in[B * CAT];       // fp32 [embedded | h0] (attn path stays fp32)
__device__ __nv_bfloat16 g_comb_bf16[B * CAT];     // bf16 [embedded | ctx]
__device__ __nv_bfloat16 g_h0_bf16[B * HD];        // bf16 hidden
__device__ float         g_attn_logits[B * L];
__device__ float         g_x[B * HE];              // comb accumulator (pre-relu), bias-init
__device__ __nv_bfloat16 g_xr_bf16[B * HE];        // bf16(relu(g_x))
__device__ float         g_gi[B * G3];
__device__ float         g_gh[B * G3];
__device__ float         g_logits[B * V];
__device__ __nv_bfloat16 g_h_bf16[B * HD];
#define NCH 8
#define CH  6288                                    // 8*6288 >= V, multiple of 16
__device__ float         g_pmax[B * NCH];
__device__ float         g_psum[B * NCH];

// ---------------- kernel: embedding lookup + concat builds ------------------
__global__ void embed_concat_kernel(const int* __restrict__ idx,
                                    const float* __restrict__ hidden,
                                    const float* __restrict__ emb_table) {
    int b = blockIdx.x;
    int row = idx[b];
    for (int k = threadIdx.x; k < EMB; k += blockDim.x) {
        float e = emb_table[(size_t)row * EMB + k];
        g_attn_in[b * CAT + k] = e;
        g_comb_bf16[b * CAT + k] = __float2bfloat16(e);
        float h = hidden[b * HD + k];
        g_attn_in[b * CAT + EMB + k] = h;
        g_h0_bf16[b * HD + k] = __float2bfloat16(h);
    }
}

// ---------------- bias init for atomic-epilogue GEMMs -----------------------
#define SEG0 (B * L)
#define SEG1 (SEG0 + B * HE)
#define SEG2 (SEG1 + B * G3)
#define SEG3 (SEG2 + B * G3)
__global__ void init_bias_kernel(const float* __restrict__ attn_b,
                                 const float* __restrict__ comb_b,
                                 const float* __restrict__ b_ih,
                                 const float* __restrict__ b_hh) {
    int i = blockIdx.x * 256 + threadIdx.x;
    if (i < SEG0) {
        g_attn_logits[i] = attn_b[i & (L - 1)];
    } else if (i < SEG1) {
        int j = i - SEG0; g_x[j] = comb_b[j & (HE - 1)];
    } else if (i < SEG2) {
        int j = i - SEG1; g_gi[j] = b_ih[j % G3];
    } else if (i < SEG3) {
        int j = i - SEG2; g_gh[j] = b_hh[j % G3];
    }
}

// ------ fp32 K-split SGEMM (attention logits only, exact path) --------------
__global__ void gemm_ksplit_kernel(const float* __restrict__ A,
                                   const float* __restrict__ W,
                                   float* __restrict__ C,
                                   int N, int K, int Kc) {
    __shared__ float As[16][64 + 4];
    __shared__ float Ws[16][64 + 4];

    const int tid = threadIdx.x;
    const int n0  = blockIdx.x * 64;
    const int kbase = blockIdx.y * Kc;
    const int lr  = tid >> 2;
    const int lk  = (tid & 3) * 4;
    const int tx  = tid & 15;
    const int ty  = tid >> 4;

    float acc[4][4];
#pragma unroll
    for (int i = 0; i < 4; i++)
#pragma unroll
        for (int j = 0; j < 4; j++) acc[i][j] = 0.0f;

    for (int k0 = kbase; k0 < kbase + Kc; k0 += 16) {
        float4 a4 = *reinterpret_cast<const float4*>(&A[(size_t)lr * K + k0 + lk]);
        As[lk + 0][lr] = a4.x; As[lk + 1][lr] = a4.y;
        As[lk + 2][lr] = a4.z; As[lk + 3][lr] = a4.w;
        float4 w4 = make_float4(0.f, 0.f, 0.f, 0.f);
        int n = n0 + lr;
        if (n < N)
            w4 = *reinterpret_cast<const float4*>(&W[(size_t)n * K + k0 + lk]);
        Ws[lk + 0][lr] = w4.x; Ws[lk + 1][lr] = w4.y;
        Ws[lk + 2][lr] = w4.z; Ws[lk + 3][lr] = w4.w;
        __syncthreads();

#pragma unroll
        for (int k = 0; k < 16; k++) {
            float4 av = *reinterpret_cast<const float4*>(&As[k][ty * 4]);
            float4 wv = *reinterpret_cast<const float4*>(&Ws[k][tx * 4]);
            float am[4] = {av.x, av.y, av.z, av.w};
            float wn[4] = {wv.x, wv.y, wv.z, wv.w};
#pragma unroll
            for (int i = 0; i < 4; i++)
#pragma unroll
                for (int j = 0; j < 4; j++)
                    acc[i][j] = fmaf(am[i], wn[j], acc[i][j]);
        }
        __syncthreads();
    }

#pragma unroll
    for (int j = 0; j < 4; j++) {
        int n = n0 + tx * 4 + j;
        if (n >= N) continue;
#pragma unroll
        for (int i = 0; i < 4; i++)
            atomicAdd(&C[(size_t)(ty * 4 + i) * N + n], acc[i][j]);
    }
}

// ================= bf16 MMA GEMM, 4-stage cp.async pipeline =================
// C[64, N] (+)= A_bf16[64, K] @ W_f32[N, K]^T, BN=128, BK=32.
// W staged fp32 in smem (zfill OOB), converted to bf16 at fragment build.
#define ST  4
#define SWS 36
#define SAS 40
#define GEMM_SMEM (ST * 128 * SWS * 4 + ST * 64 * SAS * 2)

__device__ __forceinline__ void cp16(void* saddr, const void* g, bool p) {
    uint32_t s = (uint32_t)__cvta_generic_to_shared(saddr);
    int sz = p ? 16 : 0;
    asm volatile("cp.async.cg.shared.global [%0], [%1], 16, %2;\n"
                 :: "r"(s), "l"(g), "r"(sz));
}
__device__ __forceinline__ unsigned packbf(float a, float b) {
    __nv_bfloat162 p = __float22bfloat162_rn(make_float2(a, b));
    return *reinterpret_cast<unsigned*>(&p);
}

template <bool ATOMIC>
__global__ void __launch_bounds__(256)
gemm_mma_kernel(const __nv_bfloat16* __restrict__ A,
                const float* __restrict__ W,
                const float* __restrict__ bias,
                float* __restrict__ C,
                int N, int K, int Kc) {
    extern __shared__ unsigned char dyn[];
    float* sWb = (float*)dyn;                                        // [ST][128][SWS]
    __nv_bfloat16* sAb = (__nv_bfloat16*)(dyn + ST * 128 * SWS * 4); // [ST][64][SAS]

    const int tid = threadIdx.x;
    const int n0 = blockIdx.x * 128;
    const int kbase = blockIdx.y * Kc;
    const int NIT = Kc >> 5;
    const int wid = tid >> 5, lane = tid & 31;
    const int wm = wid & 1, wn = wid >> 1;
    const int g = lane >> 2, t = lane & 3;

    float acc[2][4][4];
#pragma unroll
    for (int i = 0; i < 2; i++)
#pragma unroll
        for (int j = 0; j < 4; j++)
#pragma unroll
            for (int c = 0; c < 4; c++) acc[i][j][c] = 0.0f;

    auto load_stage = [&](int s, int k0) {
#pragma unroll
        for (int r = 0; r < 4; r++) {
            int idx = tid + 256 * r;
            int row = idx >> 3, c4 = (idx & 7) << 2;
            bool p = (n0 + row) < N;
            const float* src = W + (size_t)(n0 + row) * K + k0 + c4;
            cp16(sWb + ((s * 128 + row) * SWS + c4), p ? src : W, p);
        }
        int arow = tid >> 2, ac8 = (tid & 3) << 3;
        cp16(sAb + ((s * 64 + arow) * SAS + ac8), A + (size_t)arow * K + k0 + ac8, true);
    };

    auto compute = [&](int s) {
#pragma unroll
        for (int kb = 0; kb < 32; kb += 16) {
            unsigned a[2][4];
#pragma unroll
            for (int i = 0; i < 2; i++) {
                int r = 32 * wm + 16 * i + g;
                const __nv_bfloat16* base = sAb + (size_t)(s * 64) * SAS;
                a[i][0] = *reinterpret_cast<const unsigned*>(base + r * SAS + kb + 2 * t);
                a[i][1] = *reinterpret_cast<const unsigned*>(base + (r + 8) * SAS + kb + 2 * t);
                a[i][2] = *reinterpret_cast<const unsigned*>(base + r * SAS + kb + 2 * t + 8);
                a[i][3] = *reinterpret_cast<const unsigned*>(base + (r + 8) * SAS + kb + 2 * t + 8);
            }
#pragma unroll
            for (int j = 0; j < 4; j++) {
                int br = 32 * wn + 8 * j + g;
                const float* wrow = sWb + (size_t)(s * 128 + br) * SWS;
                float2 f01 = *reinterpret_cast<const float2*>(wrow + kb + 2 * t);
                float2 f23 = *reinterpret_cast<const float2*>(wrow + kb + 2 * t + 8);
                unsigned b0 = packbf(f01.x, f01.y);
                unsigned b1 = packbf(f23.x, f23.y);
#pragma unroll
                for (int i = 0; i < 2; i++) {
                    asm volatile(
                        "mma.sync.aligned.m16n8k16.row.col.f32.bf16.bf16.f32 "
                        "{%0,%1,%2,%3}, {%4,%5,%6,%7}, {%8,%9}, {%0,%1,%2,%3};"
                        : "+f"(acc[i][j][0]), "+f"(acc[i][j][1]),
                          "+f"(acc[i][j][2]), "+f"(acc[i][j][3])
                        : "r"(a[i][0]), "r"(a[i][1]), "r"(a[i][2]), "r"(a[i][3]),
                          "r"(b0), "r"(b1));
                }
            }
        }
    };

    // prologue: ST-1 stages in flight
#pragma unroll
    for (int s = 0; s < ST - 1; s++) {
        if (s < NIT) load_stage(s, kbase + s * 32);
        asm volatile("cp.async.commit_group;\n");
    }
#pragma unroll 1
    for (int it = 0; it < NIT; it++) {
        int pre = it + ST - 1;
        if (pre < NIT) load_stage(pre & (ST - 1), kbase + pre * 32);
        asm volatile("cp.async.commit_group;\n");
        asm volatile("cp.async.wait_group %0;\n" :: "n"(ST - 1));
        __syncthreads();
        compute(it & (ST - 1));
        __syncthreads();
    }

    // epilogue
#pragma unroll
    for (int i = 0; i < 2; i++) {
        int m = 32 * wm + 16 * i + g;
#pragma unroll
        for (int j = 0; j < 4; j++) {
            int n = n0 + 32 * wn + 8 * j + 2 * t;
            if (ATOMIC) {
                if (n < N) {
                    atomicAdd(&C[(size_t)m * N + n],       acc[i][j][0]);
                    atomicAdd(&C[(size_t)(m + 8) * N + n], acc[i][j][2]);
                }
                if (n + 1 < N) {
                    atomicAdd(&C[(size_t)m * N + n + 1],       acc[i][j][1]);
                    atomicAdd(&C[(size_t)(m + 8) * N + n + 1], acc[i][j][3]);
                }
            } else {
                if (n < N) {
                    float bv = bias[n];
                    C[(size_t)m * N + n]       = acc[i][j][0] + bv;
                    C[(size_t)(m + 8) * N + n] = acc[i][j][2] + bv;
                }
                if (n + 1 < N) {
                    float bv = bias[n + 1];
                    C[(size_t)m * N + n + 1]       = acc[i][j][1] + bv;
                    C[(size_t)(m + 8) * N + n + 1] = acc[i][j][3] + bv;
                }
            }
        }
    }
}

// ---------------- attention softmax over L=128 ------------------------------
__global__ void attn_softmax_kernel(float* __restrict__ out_attn) {
    int b = blockIdx.x;
    int t = threadIdx.x;
    __shared__ float red[4];
    float v = g_attn_logits[b * L + t];
    float m = v;
#pragma unroll
    for (int o = 16; o; o >>= 1) m = fmaxf(m, __shfl_xor_sync(0xffffffffu, m, o));
    if ((t & 31) == 0) red[t >> 5] = m;
    __syncthreads();
    m = fmaxf(fmaxf(red[0], red[1]), fmaxf(red[2], red[3]));
    __syncthreads();
    float e = expf(v - m);
    float s = e;
#pragma unroll
    for (int o = 16; o; o >>= 1) s += __shfl_xor_sync(0xffffffffu, s, o);
    if ((t & 31) == 0) red[t >> 5] = s;
    __syncthreads();
    s = red[0] + red[1] + red[2] + red[3];
    out_attn[b * L + t] = e / s;
}

// ---------------- context -> bf16 half of comb input ------------------------
__global__ void context_kernel(const float* __restrict__ enc,
                               const float* __restrict__ attn) {
    int b = blockIdx.x;
    int e = blockIdx.y * 256 + threadIdx.x;
    __shared__ float aw[L];
    if (threadIdx.x < L) aw[threadIdx.x] = attn[b * L + threadIdx.x];
    __syncthreads();
    float s = 0.0f;
#pragma unroll 8
    for (int l = 0; l < L; l++)
        s = fmaf(aw[l], enc[((size_t)l * B + b) * HE + e], s);
    g_comb_bf16[b * CAT + EMB + e] = __float2bfloat16(s);
}

// ---------------- relu + bf16 convert of comb output ------------------------
__global__ void relu_cvt_kernel() {
    int i = blockIdx.x * 1024 + threadIdx.x;
    if (i < B * HE) g_xr_bf16[i] = __float2bfloat16(fmaxf(g_x[i], 0.0f));
}

// ---------------- GRU elementwise -------------------------------------------
__global__ void gru_kernel(const float* __restrict__ hidden,
                           float* __restrict__ hnew_out) {
    int b = blockIdx.x;
    for (int j = threadIdx.x; j < HD; j += blockDim.x) {
        float ir = g_gi[b * G3 + j];
        float iz = g_gi[b * G3 + HD + j];
        float in_ = g_gi[b * G3 + 2 * HD + j];
        float hr = g_gh[b * G3 + j];
        float hz = g_gh[b * G3 + HD + j];
        float hn = g_gh[b * G3 + 2 * HD + j];
        float r = 1.0f / (1.0f + expf(-(ir + hr)));
        float z = 1.0f / (1.0f + expf(-(iz + hz)));
        float n = tanhf(in_ + r * hn);
        float h0 = hidden[b * HD + j];
        float h = (1.0f - z) * n + z * h0;
        hnew_out[b * HD + j] = h;
        g_h_bf16[b * HD + j] = __float2bfloat16(h);
    }
}

// ---------------- log_softmax: per-chunk partial stats -----------------------
__global__ void ls_partial_kernel() {
    int b = blockIdx.x, c = blockIdx.y, t = threadIdx.x;
    int s0 = c * CH, s1 = min(s0 + CH, V);
    const float* row = &g_logits[(size_t)b * V];
    __shared__ float red[8];

    float m = -INFINITY;
    for (int i = s0 + t; i < s1; i += 256) m = fmaxf(m, row[i]);
#pragma unroll
    for (int o = 16; o; o >>= 1) m = fmaxf(m, __shfl_xor_sync(0xffffffffu, m, o));
    if ((t & 31) == 0) red[t >> 5] = m;
    __syncthreads();
    float M = red[0];
#pragma unroll
    for (int w = 1; w < 8; w++) M = fmaxf(M, red[w]);
    __syncthreads();

    float s = 0.0f;
    for (int i = s0 + t; i < s1; i += 256) s += expf(row[i] - M);
#pragma unroll
    for (int o = 16; o; o >>= 1) s += __shfl_xor_sync(0xffffffffu, s, o);
    if ((t & 31) == 0) red[t >> 5] = s;
    __syncthreads();
    if (t == 0) {
        float S = 0.0f;
#pragma unroll
        for (int w = 0; w < 8; w++) S += red[w];
        g_pmax[b * NCH + c] = M;
        g_psum[b * NCH + c] = S;
    }
}

// ---------------- log_softmax: finalize --------------------------------------
__global__ void ls_final_kernel(float* __restrict__ out) {
    int b = blockIdx.x, c = blockIdx.y, t = threadIdx.x;
    __shared__ float lse_s;
    if (t == 0) {
        float M = -INFINITY;
#pragma unroll
        for (int k = 0; k < NCH; k++) M = fmaxf(M, g_pmax[b * NCH + k]);
        float S = 0.0f;
#pragma unroll
        for (int k = 0; k < NCH; k++)
            S += g_psum[b * NCH + k] * expf(g_pmax[b * NCH + k] - M);
        lse_s = M + logf(S);
    }
    __syncthreads();
    float lse = lse_s;
    int s0 = c * CH, s1 = min(s0 + CH, V);
    const float* row = &g_logits[(size_t)b * V];
    float* orow = &out[(size_t)b * V];
    for (int i = s0 + t; i < s1; i += 256) orow[i] = row[i] - lse;
}

// ---------------- launcher --------------------------------------------------
extern "C" void kernel_launch(void* const* d_in, const int* in_sizes, int n_in,
                              void* d_out, int out_size) {
    const int*   input_tensor = (const int*)  d_in[0];
    const float* hidden       = (const float*)d_in[1];
    const float* enc          = (const float*)d_in[2];
    const float* emb_table    = (const float*)d_in[4];
    const float* attn_w       = (const float*)d_in[5];
    const float* attn_b       = (const float*)d_in[6];
    const float* comb_w       = (const float*)d_in[7];
    const float* comb_b       = (const float*)d_in[8];
    const float* w_ih         = (const float*)d_in[9];
    const float* w_hh         = (const float*)d_in[10];
    const float* b_ih         = (const float*)d_in[11];
    const float* b_hh         = (const float*)d_in[12];
    const float* out_w        = (const float*)d_in[13];
    const float* out_b        = (const float*)d_in[14];

    float* out        = (float*)d_out;
    float* out_logsm  = out;
    float* out_hnew   = out + (size_t)B * V;
    float* out_attn   = out + (size_t)B * V + (size_t)B * HD;

    float* d_attn_in;     cudaGetSymbolAddress((void**)&d_attn_in,     g_attn_in);
    float* d_attn_logits; cudaGetSymbolAddress((void**)&d_attn_logits, g_attn_logits);
    float* d_x;           cudaGetSymbolAddress((void**)&d_x,           g_x);
    float* d_gi;          cudaGetSymbolAddress((void**)&d_gi,          g_gi);
    float* d_gh;          cudaGetSymbolAddress((void**)&d_gh,          g_gh);
    float* d_logits;      cudaGetSymbolAddress((void**)&d_logits,      g_logits);
    __nv_bfloat16* d_comb_bf; cudaGetSymbolAddress((void**)&d_comb_bf, g_comb_bf16);
    __nv_bfloat16* d_h0_bf;   cudaGetSymbolAddress((void**)&d_h0_bf,   g_h0_bf16);
    __nv_bfloat16* d_xr_bf;   cudaGetSymbolAddress((void**)&d_xr_bf,   g_xr_bf16);
    __nv_bfloat16* d_h_bf;    cudaGetSymbolAddress((void**)&d_h_bf,    g_h_bf16);

    static bool attr_set = false;
    if (!attr_set) {
        cudaFuncSetAttribute(gemm_mma_kernel<false>,
                             cudaFuncAttributeMaxDynamicSharedMemorySize, GEMM_SMEM);
        cudaFuncSetAttribute(gemm_mma_kernel<true>,
                             cudaFuncAttributeMaxDynamicSharedMemorySize, GEMM_SMEM);
        attr_set = true;
    }

    // 1. embedding + concats (+ bf16 copies), bias init
    embed_concat_kernel<<<B, 256>>>(input_tensor, hidden, emb_table);
    init_bias_kernel<<<(SEG3 + 255) / 256, 256>>>(attn_b, comb_b, b_ih, b_hh);

    // 2. GRU hidden GEMM (bf16 mma, k-split atomic) — independent, run early
    gemm_mma_kernel<true><<<dim3(G3 / 128, 4), 256, GEMM_SMEM>>>(
        d_h0_bf, w_hh, nullptr, d_gh, G3, HD, HD / 4);

    // 3. attention logits (fp32 exact, heavy k-split)
    gemm_ksplit_kernel<<<dim3(L / 64, 32), 256>>>(d_attn_in, attn_w,
                                                  d_attn_logits, L, CAT, CAT / 32);

    // 4. softmax over L
    attn_softmax_kernel<<<B, L>>>(out_attn);

    // 5. context -> bf16 comb input
    context_kernel<<<dim3(B, 4), 256>>>(enc, out_attn);

    // 6. comb GEMM (bf16 mma, atomic into bias-initialized g_x)
    gemm_mma_kernel<true><<<dim3(HE / 128, 8), 256, GEMM_SMEM>>>(
        d_comb_bf, comb_w, nullptr, d_x, HE, CAT, CAT / 8);

    // 7. relu + bf16 convert
    relu_cvt_kernel<<<(B * HE + 1023) / 1024, 1024>>>();

    // 8. GRU input GEMM
    gemm_mma_kernel<true><<<dim3(G3 / 128, 4), 256, GEMM_SMEM>>>(
        d_xr_bf, w_ih, nullptr, d_gi, G3, HE, HE / 4);

    // 9. GRU elementwise -> h_new fp32 + bf16
    gru_kernel<<<B, 256>>>(hidden, out_hnew);

    // 10. output projection (bf16 mma, 4-stage cp.async)
    gemm_mma_kernel<false><<<dim3((V + 127) / 128, 1), 256, GEMM_SMEM>>>(
        d_h_bf, out_w, out_b, d_logits, V, HD, HD);

    // 11-12. log_softmax (partials + finalize)
    ls_partial_kernel<<<dim3(B, NCH), 256>>>();
    ls_final_kernel<<<dim3(B, NCH), 256>>>(out_logsm);
}